// round 1
// baseline (speedup 1.0000x reference)
#include <cuda_runtime.h>
#include <math.h>

#define NN 100000
#define NE 400000
#define NG 4000
#define NF 39
#define DMAX 1024
#define BN_EPS 1e-5f

// ---------------- static device scratch (no allocation allowed) ----------------
__device__ float g_dis[NN];                     // degree -> rsqrt(degree)
__device__ float g_norm[NE];                    // per-edge norm
__device__ float g_bufA[(size_t)NN * DMAX];
__device__ float g_bufB[(size_t)NN * DMAX];
__device__ float g_bufC[(size_t)NN * DMAX];
__device__ float g_colsum[DMAX];
__device__ float g_colsq[DMAX];
__device__ float g_scale[DMAX];
__device__ float g_shift[DMAX];
__device__ float g_gate[NN];
__device__ int   g_gs[NG];
__device__ int   g_ge[NG];
__device__ float g_pooled[(size_t)NG * DMAX];
__device__ float g_h2[NG * 128];
__device__ float g_h3[NG * 16];

// ---------------- utility kernels ----------------
__global__ void k_fillf(float* p, float v, int n) {
    for (int i = blockIdx.x * blockDim.x + threadIdx.x; i < n; i += gridDim.x * blockDim.x)
        p[i] = v;
}
__global__ void k_filli(int* p, int v, int n) {
    for (int i = blockIdx.x * blockDim.x + threadIdx.x; i < n; i += gridDim.x * blockDim.x)
        p[i] = v;
}

// ---------------- degree / norm ----------------
__global__ void k_edge_deg(const int* __restrict__ col, float* deg) {
    int e = blockIdx.x * blockDim.x + threadIdx.x;
    if (e < NE) atomicAdd(&deg[col[e]], 1.0f);
}
__global__ void k_rsqrt_ip(float* p, int n) {
    int i = blockIdx.x * blockDim.x + threadIdx.x;
    if (i < n) p[i] = rsqrtf(p[i]);
}
__global__ void k_edge_norm(const int* __restrict__ row, const int* __restrict__ col,
                            const float* __restrict__ dis, float* __restrict__ norm) {
    int e = blockIdx.x * blockDim.x + threadIdx.x;
    if (e < NE) norm[e] = dis[row[e]] * dis[col[e]];
}

// ---------------- propagation: out = A * in  (A = sym-norm adj + selfloops) ------
__global__ void k_self_init(const float* __restrict__ in, float* __restrict__ out,
                            const float* __restrict__ dis, int dim, int total) {
    int idx = blockIdx.x * blockDim.x + threadIdx.x;
    if (idx >= total) return;
    int i = idx / dim;
    float s = dis[i];
    out[idx] = s * s * in[idx];
}
__global__ void k_edge_prop(const float* __restrict__ in, float* __restrict__ out,
                            const int* __restrict__ row, const int* __restrict__ col,
                            const float* __restrict__ norm, int dim, int total) {
    int t = blockIdx.x * blockDim.x + threadIdx.x;
    if (t >= total) return;
    int e = t / dim;
    int d = t - e * dim;
    int r = row[e];
    int c = col[e];
    atomicAdd(&out[(size_t)c * dim + d], norm[e] * in[(size_t)r * dim + d]);
}

// ---------------- generic tiled SGEMM: C = A[MxK] * B[KxN] (+bias)(+relu) -------
// ep: 0 = none, 1 = +bias, 2 = +bias, relu
__global__ void k_sgemm(const float* __restrict__ A, const float* __restrict__ B,
                        const float* __restrict__ bias, float* __restrict__ C,
                        int M, int N, int K, int ep) {
    __shared__ float As[16][65];
    __shared__ float Bs[16][64];
    int bm = blockIdx.y * 64;
    int bn = blockIdx.x * 64;
    int tid = threadIdx.x;  // 256 threads
    float acc[4][4] = {};
    for (int k0 = 0; k0 < K; k0 += 16) {
#pragma unroll
        for (int i = 0; i < 4; i++) {
            int idx = tid + i * 256;     // 0..1023
            int m = idx >> 4, k = idx & 15;
            As[k][m] = (bm + m < M && k0 + k < K) ? A[(size_t)(bm + m) * K + k0 + k] : 0.f;
        }
#pragma unroll
        for (int i = 0; i < 4; i++) {
            int idx = tid + i * 256;
            int n = idx & 63, k = idx >> 6;
            Bs[k][n] = (k0 + k < K && bn + n < N) ? B[(size_t)(k0 + k) * N + bn + n] : 0.f;
        }
        __syncthreads();
        int tx = tid & 15, ty = tid >> 4;
#pragma unroll
        for (int k = 0; k < 16; k++) {
            float a[4], b[4];
#pragma unroll
            for (int i = 0; i < 4; i++) a[i] = As[k][ty * 4 + i];
#pragma unroll
            for (int j = 0; j < 4; j++) b[j] = Bs[k][tx * 4 + j];
#pragma unroll
            for (int i = 0; i < 4; i++)
#pragma unroll
                for (int j = 0; j < 4; j++) acc[i][j] = fmaf(a[i], b[j], acc[i][j]);
        }
        __syncthreads();
    }
    int tx = tid & 15, ty = tid >> 4;
#pragma unroll
    for (int i = 0; i < 4; i++) {
        int m = bm + ty * 4 + i;
        if (m >= M) continue;
#pragma unroll
        for (int j = 0; j < 4; j++) {
            int n = bn + tx * 4 + j;
            if (n >= N) continue;
            float v = acc[i][j];
            if (ep >= 1) v += bias[n];
            if (ep == 2) v = fmaxf(v, 0.f);
            C[(size_t)m * N + n] = v;
        }
    }
}

// ---------------- bias + relu (in place) + column stats --------------------------
// blockDim = (32, 8); grid = (ROWBLK, ncols/32). ncols must be multiple of 32.
__global__ void k_bias_relu_stats(float* __restrict__ y, const float* __restrict__ b,
                                  float* __restrict__ colsum, float* __restrict__ colsq,
                                  int nrows, int ncols) {
    int col = blockIdx.y * 32 + threadIdx.x;
    float bb = b[col];
    float s = 0.f, sq = 0.f;
    int stride = gridDim.x * 8;
    for (int r = blockIdx.x * 8 + threadIdx.y; r < nrows; r += stride) {
        size_t idx = (size_t)r * ncols + col;
        float v = y[idx] + bb;
        v = fmaxf(v, 0.f);
        y[idx] = v;
        s += v;
        sq += v * v;
    }
    __shared__ float sh[8][33];
    __shared__ float sh2[8][33];
    sh[threadIdx.y][threadIdx.x] = s;
    sh2[threadIdx.y][threadIdx.x] = sq;
    __syncthreads();
    if (threadIdx.y == 0) {
        float ts = 0.f, tq = 0.f;
#pragma unroll
        for (int yy = 0; yy < 8; yy++) { ts += sh[yy][threadIdx.x]; tq += sh2[yy][threadIdx.x]; }
        atomicAdd(&colsum[col], ts);
        atomicAdd(&colsq[col], tq);
    }
}

__global__ void k_mkscale(const float* __restrict__ colsum, const float* __restrict__ colsq,
                          const float* __restrict__ g, const float* __restrict__ be,
                          float* __restrict__ scale, float* __restrict__ shift,
                          float invn, int ncols) {
    int c = blockIdx.x * blockDim.x + threadIdx.x;
    if (c >= ncols) return;
    float mean = colsum[c] * invn;
    float var = colsq[c] * invn - mean * mean;
    float sc = g[c] * rsqrtf(var + BN_EPS);
    scale[c] = sc;
    shift[c] = be[c] - mean * sc;
}

__global__ void k_bn_apply(float* __restrict__ y, const float* __restrict__ scale,
                           const float* __restrict__ shift, int ncols, int total) {
    int idx = blockIdx.x * blockDim.x + threadIdx.x;
    if (idx >= total) return;
    int c = idx % ncols;
    y[idx] = y[idx] * scale[c] + shift[c];
}

// ---------------- pooling ----------------
__global__ void k_gate(const float* __restrict__ x, const float* __restrict__ gw,
                       const float* __restrict__ gb, float* __restrict__ gate) {
    int warp = (blockIdx.x * blockDim.x + threadIdx.x) >> 5;
    int lane = threadIdx.x & 31;
    if (warp >= NN) return;
    const float4* xr = (const float4*)(x + (size_t)warp * 1024);
    const float4* w4 = (const float4*)gw;
    float acc = 0.f;
#pragma unroll
    for (int k = 0; k < 8; k++) {
        float4 a = xr[lane + k * 32];
        float4 b = w4[lane + k * 32];
        acc += a.x * b.x + a.y * b.y + a.z * b.z + a.w * b.w;
    }
#pragma unroll
    for (int o = 16; o > 0; o >>= 1) acc += __shfl_down_sync(0xffffffffu, acc, o);
    if (lane == 0) gate[warp] = acc + gb[0];
}

__global__ void k_bounds(const int* __restrict__ batch, int* gs, int* ge) {
    int i = blockIdx.x * blockDim.x + threadIdx.x;
    if (i >= NN) return;
    int b = batch[i];
    atomicMin(&gs[b], i);
    atomicMax(&ge[b], i + 1);
}

// one block (256 threads) per graph; batch is sorted so [s,e) is contiguous
__global__ void k_pool(const float* __restrict__ x, const float* __restrict__ gate,
                       const int* __restrict__ gs, const int* __restrict__ ge,
                       float* __restrict__ pooled) {
    int g = blockIdx.x;
    int s = gs[g], e = ge[g];
    int tid = threadIdx.x;
    __shared__ float red[256];
    // max
    float m = -INFINITY;
    for (int i = s + tid; i < e; i += 256) m = fmaxf(m, gate[i]);
    red[tid] = m;
    __syncthreads();
    for (int o = 128; o > 0; o >>= 1) {
        if (tid < o) red[tid] = fmaxf(red[tid], red[tid + o]);
        __syncthreads();
    }
    float gm = red[0];
    __syncthreads();
    // sum exp
    float ssum = 0.f;
    for (int i = s + tid; i < e; i += 256) ssum += expf(gate[i] - gm);
    red[tid] = ssum;
    __syncthreads();
    for (int o = 128; o > 0; o >>= 1) {
        if (tid < o) red[tid] += red[tid + o];
        __syncthreads();
    }
    float inv = (e > s) ? 1.0f / red[0] : 0.f;
    // weighted feature sum: each thread owns one float4 of the 1024 dims
    int d = tid * 4;
    float4 acc = make_float4(0.f, 0.f, 0.f, 0.f);
    for (int i = s; i < e; i++) {
        float w = expf(gate[i] - gm) * inv;
        float4 v = *(const float4*)&x[(size_t)i * 1024 + d];
        acc.x += w * v.x;
        acc.y += w * v.y;
        acc.z += w * v.z;
        acc.w += w * v.w;
    }
    *(float4*)&pooled[(size_t)g * 1024 + d] = acc;
}

// ---------------- host orchestration ----------------
static inline int cdiv(long a, long b) { return (int)((a + b - 1) / b); }

static void propagate(const float* in, float* out, const int* row, const int* col,
                      const float* dis, const float* norm, int dim) {
    int total = NN * dim;
    k_self_init<<<cdiv(total, 256), 256>>>(in, out, dis, dim, total);
    int etotal = NE * dim;
    k_edge_prop<<<cdiv(etotal, 256), 256>>>(in, out, row, col, norm, dim, etotal);
}

static void gemm(const float* A, const float* B, const float* bias, float* C,
                 int M, int N, int K, int ep) {
    dim3 grid(cdiv(N, 64), cdiv(M, 64));
    k_sgemm<<<grid, 256>>>(A, B, bias, C, M, N, K, ep);
}

static void post_bn(float* buf, const float* b, const float* g, const float* be,
                    float* colsum, float* colsq, float* scale, float* shift, int dout) {
    k_fillf<<<8, 256>>>(colsum, 0.f, dout);
    k_fillf<<<8, 256>>>(colsq, 0.f, dout);
    dim3 grid(128, dout / 32);
    dim3 blk(32, 8);
    k_bias_relu_stats<<<grid, blk>>>(buf, b, colsum, colsq, NN, dout);
    k_mkscale<<<cdiv(dout, 256), 256>>>(colsum, colsq, g, be, scale, shift, 1.0f / NN, dout);
    int total = NN * dout;
    k_bn_apply<<<cdiv(total, 256), 256>>>(buf, scale, shift, dout, total);
}

extern "C" void kernel_launch(void* const* d_in, const int* in_sizes, int n_in,
                              void* d_out, int out_size) {
    (void)in_sizes; (void)n_in; (void)out_size;
    const float* x_in  = (const float*)d_in[0];
    const int*   ei    = (const int*)d_in[1];
    const int*   batch = (const int*)d_in[2];
    const float *W[5], *bb[5], *gg[5], *be[5];
    for (int l = 0; l < 5; l++) {
        W[l]  = (const float*)d_in[3 + 4 * l];
        bb[l] = (const float*)d_in[4 + 4 * l];
        gg[l] = (const float*)d_in[5 + 4 * l];
        be[l] = (const float*)d_in[6 + 4 * l];
    }
    const float* gate_W = (const float*)d_in[23];
    const float* gate_b = (const float*)d_in[24];
    const float* fc2_W  = (const float*)d_in[25];
    const float* fc2_b  = (const float*)d_in[26];
    const float* fc3_W  = (const float*)d_in[27];
    const float* fc3_b  = (const float*)d_in[28];
    const float* fc4_W  = (const float*)d_in[29];
    const float* fc4_b  = (const float*)d_in[30];
    float* out = (float*)d_out;

    float *dis, *norm, *bufA, *bufB, *bufC, *colsum, *colsq, *scale, *shift;
    float *gate, *pooled, *h2, *h3;
    int *gs, *ge;
    cudaGetSymbolAddress((void**)&dis,    g_dis);
    cudaGetSymbolAddress((void**)&norm,   g_norm);
    cudaGetSymbolAddress((void**)&bufA,   g_bufA);
    cudaGetSymbolAddress((void**)&bufB,   g_bufB);
    cudaGetSymbolAddress((void**)&bufC,   g_bufC);
    cudaGetSymbolAddress((void**)&colsum, g_colsum);
    cudaGetSymbolAddress((void**)&colsq,  g_colsq);
    cudaGetSymbolAddress((void**)&scale,  g_scale);
    cudaGetSymbolAddress((void**)&shift,  g_shift);
    cudaGetSymbolAddress((void**)&gate,   g_gate);
    cudaGetSymbolAddress((void**)&gs,     g_gs);
    cudaGetSymbolAddress((void**)&ge,     g_ge);
    cudaGetSymbolAddress((void**)&pooled, g_pooled);
    cudaGetSymbolAddress((void**)&h2,     g_h2);
    cudaGetSymbolAddress((void**)&h3,     g_h3);

    const int* row = ei;        // edge_index[0]
    const int* col = ei + NE;   // edge_index[1]

    // ---- GCN normalization ----
    k_fillf<<<256, 256>>>(dis, 1.0f, NN);             // self-loop contributes 1 to degree
    k_edge_deg<<<cdiv(NE, 256), 256>>>(col, dis);
    k_rsqrt_ip<<<cdiv(NN, 256), 256>>>(dis, NN);
    k_edge_norm<<<cdiv(NE, 256), 256>>>(row, col, dis, norm);

    // ---- Layer 1: 39 -> 1024, propagate first (39 < 1024) ----
    propagate(x_in, bufA, row, col, dis, norm, NF);
    gemm(bufA, W[0], nullptr, bufB, NN, 1024, NF, 0);
    post_bn(bufB, bb[0], gg[0], be[0], colsum, colsq, scale, shift, 1024);
    // X = bufB (1024)

    // ---- Layer 2: 1024 -> 512, gemm first ----
    gemm(bufB, W[1], nullptr, bufA, NN, 512, 1024, 0);
    propagate(bufA, bufC, row, col, dis, norm, 512);
    post_bn(bufC, bb[1], gg[1], be[1], colsum, colsq, scale, shift, 512);
    // X = bufC (512)

    // ---- Layer 3: 512 -> 256, gemm first ----
    gemm(bufC, W[2], nullptr, bufA, NN, 256, 512, 0);
    propagate(bufA, bufB, row, col, dis, norm, 256);
    post_bn(bufB, bb[2], gg[2], be[2], colsum, colsq, scale, shift, 256);
    // X = bufB (256)

    // ---- Layer 4: 256 -> 512, propagate first ----
    propagate(bufB, bufA, row, col, dis, norm, 256);
    gemm(bufA, W[3], nullptr, bufC, NN, 512, 256, 0);
    post_bn(bufC, bb[3], gg[3], be[3], colsum, colsq, scale, shift, 512);
    // X = bufC (512)

    // ---- Layer 5: 512 -> 1024, propagate first ----
    propagate(bufC, bufA, row, col, dis, norm, 512);
    gemm(bufA, W[4], nullptr, bufB, NN, 1024, 512, 0);
    post_bn(bufB, bb[4], gg[4], be[4], colsum, colsq, scale, shift, 1024);
    // X = bufB (1024)

    // ---- attentional pooling ----
    k_gate<<<cdiv(NN, 8), 256>>>(bufB, gate_W, gate_b, gate);
    k_filli<<<32, 256>>>(gs, NN, NG);
    k_filli<<<32, 256>>>(ge, 0, NG);
    k_bounds<<<cdiv(NN, 256), 256>>>(batch, gs, ge);
    k_pool<<<NG, 256>>>(bufB, gate, gs, ge, pooled);

    // ---- MLP head ----
    gemm(pooled, fc2_W, fc2_b, h2, NG, 128, 1024, 2);
    gemm(h2, fc3_W, fc3_b, h3, NG, 16, 128, 2);
    gemm(h3, fc4_W, fc4_b, out, NG, 1, 16, 1);
}

// round 2
// speedup vs baseline: 1.5401x; 1.5401x over previous
#include <cuda_runtime.h>
#include <math.h>

#define NN 100000
#define NE 400000
#define NG 4000
#define NF 39
#define DMAX 1024
#define BN_EPS 1e-5f

// ---------------- static device scratch ----------------
__device__ float g_dis[NN];
__device__ float g_norm[NE];
__device__ int   g_counts[NN];
__device__ int   g_off[NN + 1];
__device__ int   g_cursor[NN];
__device__ int   g_src[NE];
__device__ float g_w[NE];
__device__ float g_bufA[(size_t)NN * DMAX];
__device__ float g_bufB[(size_t)NN * DMAX];
__device__ float g_bufC[(size_t)NN * DMAX];
__device__ float g_colsum[DMAX];
__device__ float g_colsq[DMAX];
__device__ float g_scale[DMAX];
__device__ float g_shift[DMAX];
__device__ float g_gate[NN];
__device__ int   g_gs[NG];
__device__ int   g_ge[NG];
__device__ float g_pooled[(size_t)NG * DMAX];
__device__ float g_h2[NG * 128];
__device__ float g_h3[NG * 16];

// ---------------- utility ----------------
__global__ void k_fillf(float* p, float v, int n) {
    for (int i = blockIdx.x * blockDim.x + threadIdx.x; i < n; i += gridDim.x * blockDim.x)
        p[i] = v;
}
__global__ void k_filli(int* p, int v, int n) {
    for (int i = blockIdx.x * blockDim.x + threadIdx.x; i < n; i += gridDim.x * blockDim.x)
        p[i] = v;
}
__global__ void k_copyi(const int* __restrict__ a, int* __restrict__ b, int n) {
    for (int i = blockIdx.x * blockDim.x + threadIdx.x; i < n; i += gridDim.x * blockDim.x)
        b[i] = a[i];
}

// ---------------- CSR build ----------------
__global__ void k_histc(const int* __restrict__ col, int* counts) {
    int e = blockIdx.x * blockDim.x + threadIdx.x;
    if (e < NE) atomicAdd(&counts[col[e]], 1);
}
__global__ void k_disk(const int* __restrict__ counts, float* dis) {
    int i = blockIdx.x * blockDim.x + threadIdx.x;
    if (i < NN) dis[i] = rsqrtf((float)counts[i] + 1.0f);
}
__global__ void k_edge_norm(const int* __restrict__ row, const int* __restrict__ col,
                            const float* __restrict__ dis, float* __restrict__ norm) {
    int e = blockIdx.x * blockDim.x + threadIdx.x;
    if (e < NE) norm[e] = dis[row[e]] * dis[col[e]];
}
// single-block exclusive scan: off[0]=0, off[i+1]=sum counts[0..i]
__global__ void k_scan(const int* __restrict__ counts, int* __restrict__ off) {
    __shared__ int sh[1024];
    __shared__ int carry_s;
    int t = threadIdx.x;
    if (t == 0) { carry_s = 0; off[0] = 0; }
    __syncthreads();
    for (int base = 0; base < NN; base += 1024) {
        int i = base + t;
        int v = (i < NN) ? counts[i] : 0;
        sh[t] = v;
        __syncthreads();
        for (int o = 1; o < 1024; o <<= 1) {
            int add = (t >= o) ? sh[t - o] : 0;
            __syncthreads();
            sh[t] += add;
            __syncthreads();
        }
        int carry = carry_s;
        if (i < NN) off[i + 1] = carry + sh[t];
        __syncthreads();
        if (t == 1023) carry_s = carry + sh[1023];
        __syncthreads();
    }
}
__global__ void k_scatter(const int* __restrict__ row, const int* __restrict__ col,
                          const float* __restrict__ norm, int* cursor,
                          int* __restrict__ csr_src, float* __restrict__ csr_w) {
    int e = blockIdx.x * blockDim.x + threadIdx.x;
    if (e >= NE) return;
    int c = col[e];
    int p = atomicAdd(&cursor[c], 1);
    csr_src[p] = row[e];
    csr_w[p] = norm[e];
}

// ---------------- CSR gather propagate ----------------
// out[n] = dis[n]^2 * in[n] + sum_e w[e]*in[src[e]]   (optionally + bias, relu, stats)
template <int DIMV, int NPB, bool FUSE>
__global__ void k_prop4(const float4* __restrict__ in, float4* __restrict__ out,
                        const float* __restrict__ dis,
                        const int* __restrict__ off, const int* __restrict__ src,
                        const float* __restrict__ w,
                        const float* __restrict__ bias,
                        float* __restrict__ colsum, float* __restrict__ colsq) {
    int x = threadIdx.x;
    int yy = threadIdx.y;
    float4 bb = make_float4(0.f, 0.f, 0.f, 0.f);
    float4 s1 = make_float4(0.f, 0.f, 0.f, 0.f);
    float4 s2 = make_float4(0.f, 0.f, 0.f, 0.f);
    if (FUSE) bb = *(const float4*)&bias[x * 4];
    for (int n = blockIdx.x * NPB + yy; n < NN; n += gridDim.x * NPB) {
        float d = dis[n];
        float sc = d * d;
        float4 v = in[(size_t)n * DIMV + x];
        float4 acc = make_float4(sc * v.x, sc * v.y, sc * v.z, sc * v.w);
        int e1 = __ldg(&off[n + 1]);
        for (int e = __ldg(&off[n]); e < e1; e++) {
            int sr = __ldg(&src[e]);
            float ww = __ldg(&w[e]);
            float4 u = in[(size_t)sr * DIMV + x];
            acc.x = fmaf(ww, u.x, acc.x);
            acc.y = fmaf(ww, u.y, acc.y);
            acc.z = fmaf(ww, u.z, acc.z);
            acc.w = fmaf(ww, u.w, acc.w);
        }
        if (FUSE) {
            acc.x = fmaxf(acc.x + bb.x, 0.f);
            acc.y = fmaxf(acc.y + bb.y, 0.f);
            acc.z = fmaxf(acc.z + bb.z, 0.f);
            acc.w = fmaxf(acc.w + bb.w, 0.f);
            out[(size_t)n * DIMV + x] = acc;
            s1.x += acc.x; s1.y += acc.y; s1.z += acc.z; s1.w += acc.w;
            s2.x += acc.x * acc.x; s2.y += acc.y * acc.y;
            s2.z += acc.z * acc.z; s2.w += acc.w * acc.w;
        } else {
            out[(size_t)n * DIMV + x] = acc;
        }
    }
    if (FUSE) {
        int c = x * 4;
        atomicAdd(&colsum[c + 0], s1.x);
        atomicAdd(&colsum[c + 1], s1.y);
        atomicAdd(&colsum[c + 2], s1.z);
        atomicAdd(&colsum[c + 3], s1.w);
        atomicAdd(&colsq[c + 0], s2.x);
        atomicAdd(&colsq[c + 1], s2.y);
        atomicAdd(&colsq[c + 2], s2.z);
        atomicAdd(&colsq[c + 3], s2.w);
    }
}

// scalar propagate for dim=39 (layer 1 input)
__global__ void k_prop39(const float* __restrict__ in, float* __restrict__ out,
                         const float* __restrict__ dis,
                         const int* __restrict__ off, const int* __restrict__ src,
                         const float* __restrict__ w) {
    int x = threadIdx.x;  // 0..63
    if (x >= NF) return;
    int yy = threadIdx.y; // 0..3
    for (int n = blockIdx.x * 4 + yy; n < NN; n += gridDim.x * 4) {
        float d = dis[n];
        float acc = d * d * in[(size_t)n * NF + x];
        int e1 = __ldg(&off[n + 1]);
        for (int e = __ldg(&off[n]); e < e1; e++)
            acc = fmaf(__ldg(&w[e]), in[(size_t)__ldg(&src[e]) * NF + x], acc);
        out[(size_t)n * NF + x] = acc;
    }
}

// ---------------- 128x128 SGEMM, 256 threads, 8x8 micro-tile --------------------
// mode: 0 = raw, 1 = +bias, 2 = +bias+relu, 3 = +bias+relu+stats
__global__ void __launch_bounds__(256, 2)
k_sgemm128(const float* __restrict__ A, const float* __restrict__ B,
           const float* __restrict__ bias, float* __restrict__ C,
           int M, int N, int K, int mode,
           float* __restrict__ colsum, float* __restrict__ colsq) {
    __shared__ float As[8][132];
    __shared__ float Bs[8][132];
    __shared__ float s_sum[128];
    __shared__ float s_sq[128];
    const int bm = blockIdx.y * 128;
    const int bn = blockIdx.x * 128;
    const int tid = threadIdx.x;
    const int tx = tid & 15, ty = tid >> 4;
    const bool vecK = (K & 3) == 0;
    const bool vecN = (N & 3) == 0;

    float acc[8][8];
#pragma unroll
    for (int i = 0; i < 8; i++)
#pragma unroll
        for (int j = 0; j < 8; j++) acc[i][j] = 0.f;

    const int arow = tid >> 1, ah = tid & 1;      // A loader mapping
    const int bk = tid >> 5, bn4 = (tid & 31) * 4; // B loader mapping

    for (int k0 = 0; k0 < K; k0 += 8) {
        // load A tile -> As[k][m] (transposed)
        {
            int gm = bm + arow;
            float av[4];
            if (vecK && gm < M && k0 + ah * 4 + 3 < K) {
                float4 v = *(const float4*)&A[(size_t)gm * K + k0 + ah * 4];
                av[0] = v.x; av[1] = v.y; av[2] = v.z; av[3] = v.w;
            } else {
#pragma unroll
                for (int j = 0; j < 4; j++)
                    av[j] = (gm < M && k0 + ah * 4 + j < K)
                                ? A[(size_t)gm * K + k0 + ah * 4 + j] : 0.f;
            }
#pragma unroll
            for (int j = 0; j < 4; j++) As[ah * 4 + j][arow] = av[j];
        }
        // load B tile -> Bs[k][n]
        {
            float4 v;
            if (vecN && k0 + bk < K && bn + bn4 + 3 < N) {
                v = *(const float4*)&B[(size_t)(k0 + bk) * N + bn + bn4];
            } else {
                float bv[4];
#pragma unroll
                for (int j = 0; j < 4; j++)
                    bv[j] = (k0 + bk < K && bn + bn4 + j < N)
                                ? B[(size_t)(k0 + bk) * N + bn + bn4 + j] : 0.f;
                v = make_float4(bv[0], bv[1], bv[2], bv[3]);
            }
            *(float4*)&Bs[bk][bn4] = v;
        }
        __syncthreads();
#pragma unroll
        for (int k = 0; k < 8; k++) {
            float4 a0 = *(const float4*)&As[k][ty * 4];
            float4 a1 = *(const float4*)&As[k][64 + ty * 4];
            float4 b0 = *(const float4*)&Bs[k][tx * 4];
            float4 b1 = *(const float4*)&Bs[k][64 + tx * 4];
            float a[8] = {a0.x, a0.y, a0.z, a0.w, a1.x, a1.y, a1.z, a1.w};
            float b[8] = {b0.x, b0.y, b0.z, b0.w, b1.x, b1.y, b1.z, b1.w};
#pragma unroll
            for (int i = 0; i < 8; i++)
#pragma unroll
                for (int j = 0; j < 8; j++) acc[i][j] = fmaf(a[i], b[j], acc[i][j]);
        }
        __syncthreads();
    }

    if (mode == 3) {
        if (tid < 128) { s_sum[tid] = 0.f; s_sq[tid] = 0.f; }
        __syncthreads();
    }

    float csum[8], csq[8];
#pragma unroll
    for (int j = 0; j < 8; j++) { csum[j] = 0.f; csq[j] = 0.f; }

#pragma unroll
    for (int i = 0; i < 8; i++) {
        int mr = (i < 4) ? (ty * 4 + i) : (64 + ty * 4 + i - 4);
        int m = bm + mr;
        if (m >= M) continue;
#pragma unroll
        for (int j = 0; j < 8; j++) {
            int nc = (j < 4) ? (tx * 4 + j) : (64 + tx * 4 + j - 4);
            int n = bn + nc;
            if (n >= N) continue;
            float v = acc[i][j];
            if (mode >= 1) v += bias[n];
            if (mode >= 2) v = fmaxf(v, 0.f);
            C[(size_t)m * N + n] = v;
            if (mode == 3) { csum[j] += v; csq[j] += v * v; }
        }
    }
    if (mode == 3) {
#pragma unroll
        for (int j = 0; j < 8; j++) {
            int nc = (j < 4) ? (tx * 4 + j) : (64 + tx * 4 + j - 4);
            atomicAdd(&s_sum[nc], csum[j]);
            atomicAdd(&s_sq[nc], csq[j]);
        }
        __syncthreads();
        if (tid < 128) {
            int n = bn + tid;
            if (n < N) {
                atomicAdd(&colsum[n], s_sum[tid]);
                atomicAdd(&colsq[n], s_sq[tid]);
            }
        }
    }
}

// ---------------- BN finalize ----------------
__global__ void k_mkscale(const float* __restrict__ colsum, const float* __restrict__ colsq,
                          const float* __restrict__ g, const float* __restrict__ be,
                          float* __restrict__ scale, float* __restrict__ shift,
                          float invn, int ncols) {
    int c = blockIdx.x * blockDim.x + threadIdx.x;
    if (c >= ncols) return;
    float mean = colsum[c] * invn;
    float var = colsq[c] * invn - mean * mean;
    float sc = g[c] * rsqrtf(var + BN_EPS);
    scale[c] = sc;
    shift[c] = be[c] - mean * sc;
}
__global__ void k_bn_apply4(float4* __restrict__ y, const float* __restrict__ scale,
                            const float* __restrict__ shift, int dimv, int total4) {
    int idx = blockIdx.x * blockDim.x + threadIdx.x;
    if (idx >= total4) return;
    int c = (idx % dimv) * 4;
    float4 v = y[idx];
    v.x = v.x * scale[c + 0] + shift[c + 0];
    v.y = v.y * scale[c + 1] + shift[c + 1];
    v.z = v.z * scale[c + 2] + shift[c + 2];
    v.w = v.w * scale[c + 3] + shift[c + 3];
    y[idx] = v;
}

// ---------------- pooling ----------------
__global__ void k_gate(const float* __restrict__ x, const float* __restrict__ gw,
                       const float* __restrict__ gb, float* __restrict__ gate) {
    int warp = (blockIdx.x * blockDim.x + threadIdx.x) >> 5;
    int lane = threadIdx.x & 31;
    if (warp >= NN) return;
    const float4* xr = (const float4*)(x + (size_t)warp * 1024);
    const float4* w4 = (const float4*)gw;
    float acc = 0.f;
#pragma unroll
    for (int k = 0; k < 8; k++) {
        float4 a = xr[lane + k * 32];
        float4 b = w4[lane + k * 32];
        acc += a.x * b.x + a.y * b.y + a.z * b.z + a.w * b.w;
    }
#pragma unroll
    for (int o = 16; o > 0; o >>= 1) acc += __shfl_down_sync(0xffffffffu, acc, o);
    if (lane == 0) gate[warp] = acc + gb[0];
}
__global__ void k_bounds(const int* __restrict__ batch, int* gs, int* ge) {
    int i = blockIdx.x * blockDim.x + threadIdx.x;
    if (i >= NN) return;
    int b = batch[i];
    atomicMin(&gs[b], i);
    atomicMax(&ge[b], i + 1);
}
__global__ void k_pool(const float* __restrict__ x, const float* __restrict__ gate,
                       const int* __restrict__ gs, const int* __restrict__ ge,
                       float* __restrict__ pooled) {
    int g = blockIdx.x;
    int s = gs[g], e = ge[g];
    int tid = threadIdx.x;
    __shared__ float red[256];
    float m = -INFINITY;
    for (int i = s + tid; i < e; i += 256) m = fmaxf(m, gate[i]);
    red[tid] = m;
    __syncthreads();
    for (int o = 128; o > 0; o >>= 1) {
        if (tid < o) red[tid] = fmaxf(red[tid], red[tid + o]);
        __syncthreads();
    }
    float gm = red[0];
    __syncthreads();
    float ssum = 0.f;
    for (int i = s + tid; i < e; i += 256) ssum += expf(gate[i] - gm);
    red[tid] = ssum;
    __syncthreads();
    for (int o = 128; o > 0; o >>= 1) {
        if (tid < o) red[tid] += red[tid + o];
        __syncthreads();
    }
    float inv = (e > s) ? 1.0f / red[0] : 0.f;
    int d = tid * 4;
    float4 acc = make_float4(0.f, 0.f, 0.f, 0.f);
    for (int i = s; i < e; i++) {
        float w = expf(gate[i] - gm) * inv;
        float4 v = *(const float4*)&x[(size_t)i * 1024 + d];
        acc.x += w * v.x; acc.y += w * v.y; acc.z += w * v.z; acc.w += w * v.w;
    }
    *(float4*)&pooled[(size_t)g * 1024 + d] = acc;
}

// ---------------- host orchestration ----------------
static inline int cdiv(long a, long b) { return (int)((a + b - 1) / b); }

static void gemm(const float* A, const float* B, const float* bias, float* C,
                 int M, int N, int K, int mode, float* colsum, float* colsq) {
    dim3 grid(cdiv(N, 128), cdiv(M, 128));
    k_sgemm128<<<grid, 256>>>(A, B, bias, C, M, N, K, mode, colsum, colsq);
}

extern "C" void kernel_launch(void* const* d_in, const int* in_sizes, int n_in,
                              void* d_out, int out_size) {
    (void)in_sizes; (void)n_in; (void)out_size;
    const float* x_in  = (const float*)d_in[0];
    const int*   ei    = (const int*)d_in[1];
    const int*   batch = (const int*)d_in[2];
    const float *W[5], *bb[5], *gg[5], *be[5];
    for (int l = 0; l < 5; l++) {
        W[l]  = (const float*)d_in[3 + 4 * l];
        bb[l] = (const float*)d_in[4 + 4 * l];
        gg[l] = (const float*)d_in[5 + 4 * l];
        be[l] = (const float*)d_in[6 + 4 * l];
    }
    const float* gate_W = (const float*)d_in[23];
    const float* gate_b = (const float*)d_in[24];
    const float* fc2_W  = (const float*)d_in[25];
    const float* fc2_b  = (const float*)d_in[26];
    const float* fc3_W  = (const float*)d_in[27];
    const float* fc3_b  = (const float*)d_in[28];
    const float* fc4_W  = (const float*)d_in[29];
    const float* fc4_b  = (const float*)d_in[30];
    float* out = (float*)d_out;

    float *dis, *norm, *bufA, *bufB, *bufC, *colsum, *colsq, *scale, *shift;
    float *gate, *pooled, *h2, *h3, *csr_w;
    int *gs, *ge, *counts, *off, *cursor, *csr_src;
    cudaGetSymbolAddress((void**)&dis,     g_dis);
    cudaGetSymbolAddress((void**)&norm,    g_norm);
    cudaGetSymbolAddress((void**)&counts,  g_counts);
    cudaGetSymbolAddress((void**)&off,     g_off);
    cudaGetSymbolAddress((void**)&cursor,  g_cursor);
    cudaGetSymbolAddress((void**)&csr_src, g_src);
    cudaGetSymbolAddress((void**)&csr_w,   g_w);
    cudaGetSymbolAddress((void**)&bufA,    g_bufA);
    cudaGetSymbolAddress((void**)&bufB,    g_bufB);
    cudaGetSymbolAddress((void**)&bufC,    g_bufC);
    cudaGetSymbolAddress((void**)&colsum,  g_colsum);
    cudaGetSymbolAddress((void**)&colsq,   g_colsq);
    cudaGetSymbolAddress((void**)&scale,   g_scale);
    cudaGetSymbolAddress((void**)&shift,   g_shift);
    cudaGetSymbolAddress((void**)&gate,    g_gate);
    cudaGetSymbolAddress((void**)&gs,      g_gs);
    cudaGetSymbolAddress((void**)&ge,      g_ge);
    cudaGetSymbolAddress((void**)&pooled,  g_pooled);
    cudaGetSymbolAddress((void**)&h2,      g_h2);
    cudaGetSymbolAddress((void**)&h3,      g_h3);

    const int* row = ei;
    const int* col = ei + NE;

    // ---- GCN norm + CSR build ----
    k_filli<<<256, 256>>>(counts, 0, NN);
    k_histc<<<cdiv(NE, 256), 256>>>(col, counts);
    k_disk<<<cdiv(NN, 256), 256>>>(counts, dis);
    k_edge_norm<<<cdiv(NE, 256), 256>>>(row, col, dis, norm);
    k_scan<<<1, 1024>>>(counts, off);
    k_copyi<<<cdiv(NN, 256), 256>>>(off, cursor, NN);
    k_scatter<<<cdiv(NE, 256), 256>>>(row, col, norm, cursor, csr_src, csr_w);

    const float invn = 1.0f / NN;

    // ---- Layer 1: prop(39) -> gemm(39->1024, fused bias/relu/stats) ----
    k_prop39<<<2048, dim3(64, 4)>>>(x_in, bufA, dis, off, csr_src, csr_w);
    k_fillf<<<8, 256>>>(colsum, 0.f, 1024);
    k_fillf<<<8, 256>>>(colsq, 0.f, 1024);
    gemm(bufA, W[0], bb[0], bufB, NN, 1024, NF, 3, colsum, colsq);
    k_mkscale<<<4, 256>>>(colsum, colsq, gg[0], be[0], scale, shift, invn, 1024);
    k_bn_apply4<<<cdiv((long)NN * 256, 256), 256>>>((float4*)bufB, scale, shift, 256, NN * 256);

    // ---- Layer 2: gemm(1024->512) -> prop512 fused ----
    gemm(bufB, W[1], nullptr, bufA, NN, 512, 1024, 0, nullptr, nullptr);
    k_fillf<<<8, 256>>>(colsum, 0.f, 512);
    k_fillf<<<8, 256>>>(colsq, 0.f, 512);
    k_prop4<128, 2, true><<<2048, dim3(128, 2)>>>((const float4*)bufA, (float4*)bufC,
                                                  dis, off, csr_src, csr_w,
                                                  bb[1], colsum, colsq);
    k_mkscale<<<2, 256>>>(colsum, colsq, gg[1], be[1], scale, shift, invn, 512);
    k_bn_apply4<<<cdiv((long)NN * 128, 256), 256>>>((float4*)bufC, scale, shift, 128, NN * 128);

    // ---- Layer 3: gemm(512->256) -> prop256 fused ----
    gemm(bufC, W[2], nullptr, bufA, NN, 256, 512, 0, nullptr, nullptr);
    k_fillf<<<8, 256>>>(colsum, 0.f, 256);
    k_fillf<<<8, 256>>>(colsq, 0.f, 256);
    k_prop4<64, 4, true><<<2048, dim3(64, 4)>>>((const float4*)bufA, (float4*)bufB,
                                                dis, off, csr_src, csr_w,
                                                bb[2], colsum, colsq);
    k_mkscale<<<1, 256>>>(colsum, colsq, gg[2], be[2], scale, shift, invn, 256);
    k_bn_apply4<<<cdiv((long)NN * 64, 256), 256>>>((float4*)bufB, scale, shift, 64, NN * 64);

    // ---- Layer 4: prop256 -> gemm(256->512 fused) ----
    k_prop4<64, 4, false><<<2048, dim3(64, 4)>>>((const float4*)bufB, (float4*)bufA,
                                                 dis, off, csr_src, csr_w,
                                                 nullptr, nullptr, nullptr);
    k_fillf<<<8, 256>>>(colsum, 0.f, 512);
    k_fillf<<<8, 256>>>(colsq, 0.f, 512);
    gemm(bufA, W[3], bb[3], bufC, NN, 512, 256, 3, colsum, colsq);
    k_mkscale<<<2, 256>>>(colsum, colsq, gg[3], be[3], scale, shift, invn, 512);
    k_bn_apply4<<<cdiv((long)NN * 128, 256), 256>>>((float4*)bufC, scale, shift, 128, NN * 128);

    // ---- Layer 5: prop512 -> gemm(512->1024 fused) ----
    k_prop4<128, 2, false><<<2048, dim3(128, 2)>>>((const float4*)bufC, (float4*)bufA,
                                                   dis, off, csr_src, csr_w,
                                                   nullptr, nullptr, nullptr);
    k_fillf<<<8, 256>>>(colsum, 0.f, 1024);
    k_fillf<<<8, 256>>>(colsq, 0.f, 1024);
    gemm(bufA, W[4], bb[4], bufB, NN, 1024, 512, 3, colsum, colsq);
    k_mkscale<<<4, 256>>>(colsum, colsq, gg[4], be[4], scale, shift, invn, 1024);
    k_bn_apply4<<<cdiv((long)NN * 256, 256), 256>>>((float4*)bufB, scale, shift, 256, NN * 256);

    // ---- attentional pooling ----
    k_gate<<<cdiv(NN, 8), 256>>>(bufB, gate_W, gate_b, gate);
    k_filli<<<32, 256>>>(gs, NN, NG);
    k_filli<<<32, 256>>>(ge, 0, NG);
    k_bounds<<<cdiv(NN, 256), 256>>>(batch, gs, ge);
    k_pool<<<NG, 256>>>(bufB, gate, gs, ge, pooled);

    // ---- MLP head ----
    gemm(pooled, fc2_W, fc2_b, h2, NG, 128, 1024, 2, nullptr, nullptr);
    gemm(h2, fc3_W, fc3_b, h3, NG, 16, 128, 2, nullptr, nullptr);
    gemm(h3, fc4_W, fc4_b, out, NG, 1, 16, 1, nullptr, nullptr);
}